// round 5
// baseline (speedup 1.0000x reference)
#include <cuda_runtime.h>
#include <cstdint>

#define IN_DIM   16
#define OUT_DIM  32
#define TPB      256
#define WARPS    (TPB / 32)
#define C15      286331154u   // ceil(2^32/15); umulhi(y+7, C15) == floor((y+7)/15), y in [0,60]

__device__ uint4 g_wp[OUT_DIM];     // positive-mask bytes {0,1}, 4 chunks per output
__device__ uint4 g_wm[OUT_DIM];     // negative-mask bytes (safe path)
__device__ float g_bias[OUT_DIM];
__device__ float g_par[3];          // qa, qb, scale
__device__ int   g_haszero;

__global__ void quant_prep_kernel(const float* __restrict__ weight,
                                  const float* __restrict__ pInMin,
                                  const float* __restrict__ pInMax) {
    int o = threadIdx.x;                       // one warp
    float InMin = *pInMin, InMax = *pInMax;
    float scale = InMax - InMin;
    if (o == 0) {
        g_par[0] = 15.0f / scale;
        g_par[1] = -InMin * 15.0f / scale;
        g_par[2] = scale;
    }
    int anyz = 0, ssum = 0;
    uint32_t wp[4], wm[4];
    #pragma unroll
    for (int c = 0; c < 4; c++) {
        uint32_t p = 0, m = 0;
        #pragma unroll
        for (int j = 0; j < 4; j++) {
            float w = weight[o * IN_DIM + c * 4 + j];
            int s = (w > 0.0f) ? 1 : ((w < 0.0f) ? -1 : 0);
            ssum += s;
            anyz |= (s == 0);
            if (s > 0) p |= 1u << (8 * j);
            if (s < 0) m |= 1u << (8 * j);
        }
        wp[c] = p; wm[c] = m;
    }
    g_wp[o] = make_uint4(wp[0], wp[1], wp[2], wp[3]);
    g_wm[o] = make_uint4(wm[0], wm[1], wm[2], wm[3]);
    g_bias[o] = InMin * (float)ssum;
    unsigned zb = __ballot_sync(0xffffffffu, anyz);
    if (o == 0) g_haszero = (zb != 0u) ? 1 : 0;
}

__device__ __forceinline__ uint32_t packq(float4 x, float qa, float qb) {
    int a = __float2int_rn(fmaf(x.x, qa, qb));
    int b = __float2int_rn(fmaf(x.y, qa, qb));
    int d = __float2int_rn(fmaf(x.z, qa, qb));
    int e = __float2int_rn(fmaf(x.w, qa, qb));
    return __byte_perm(__byte_perm(a, b, 0x0040),
                       __byte_perm(d, e, 0x0040), 0x5410);
}

// term sum over 4 chunks for one output; T.c = S_c + 14, seed 7 folds round bias.
__device__ __forceinline__ int quad_fast(uint4 q, uint4 T, uint4 w) {
    unsigned rp0 = __dp4a(q.x, w.x, 7u), rm0 = T.x - rp0;
    unsigned rp1 = __dp4a(q.y, w.y, 7u), rm1 = T.y - rp1;
    unsigned rp2 = __dp4a(q.z, w.z, 7u), rm2 = T.z - rp2;
    unsigned rp3 = __dp4a(q.w, w.w, 7u), rm3 = T.w - rp3;
    return (int)__umulhi(rp0, C15) - (int)__umulhi(rm0, C15)
         + (int)__umulhi(rp1, C15) - (int)__umulhi(rm1, C15)
         + (int)__umulhi(rp2, C15) - (int)__umulhi(rm2, C15)
         + (int)__umulhi(rp3, C15) - (int)__umulhi(rm3, C15);
}

__device__ __forceinline__ int quad_safe(uint4 q, uint4 wp, uint4 wm) {
    unsigned rp0 = __dp4a(q.x, wp.x, 7u), rm0 = __dp4a(q.x, wm.x, 7u);
    unsigned rp1 = __dp4a(q.y, wp.y, 7u), rm1 = __dp4a(q.y, wm.y, 7u);
    unsigned rp2 = __dp4a(q.z, wp.z, 7u), rm2 = __dp4a(q.z, wm.z, 7u);
    unsigned rp3 = __dp4a(q.w, wp.w, 7u), rm3 = __dp4a(q.w, wm.w, 7u);
    return (int)__umulhi(rp0, C15) - (int)__umulhi(rm0, C15)
         + (int)__umulhi(rp1, C15) - (int)__umulhi(rm1, C15)
         + (int)__umulhi(rp2, C15) - (int)__umulhi(rm2, C15)
         + (int)__umulhi(rp3, C15) - (int)__umulhi(rm3, C15);
}

__global__ void __launch_bounds__(TPB)
quant_main_kernel(const float4* __restrict__ in, float4* __restrict__ out, int rows) {
    __shared__ uint32_t s_q[WARPS][128];   // 32 rows x 4 packed q chunks
    __shared__ uint32_t s_T[WARPS][128];   // 32 rows x 4 chunk sums (+14)
    __shared__ uint4    s_wp[OUT_DIM];
    __shared__ uint4    s_wm[OUT_DIM];
    __shared__ float4   s_bias[OUT_DIM / 4];

    int tid = threadIdx.x;
    int w = tid >> 5;
    int t = tid & 31;
    if (tid < OUT_DIM) { s_wp[tid] = g_wp[tid]; s_wm[tid] = g_wm[tid]; }
    if (tid < OUT_DIM / 4) s_bias[tid] = ((const float4*)g_bias)[tid];
    __syncthreads();

    const float qa = g_par[0];
    const float qb = g_par[1];
    const float scale = g_par[2];
    const int hz = g_haszero;

    int tileRow = blockIdx.x * TPB + w * 32;

    // ---- Coalesced load, quantize, stage q + T ----
    const float4* ip = in + (size_t)tileRow * 4;
    #pragma unroll
    for (int i = 0; i < 4; i++) {
        int n = i * 32 + t;                      // row*4 + chunk
        float4 x = make_float4(0.f, 0.f, 0.f, 0.f);
        if (tileRow + (n >> 2) < rows) x = ip[n];
        uint32_t qw = packq(x, qa, qb);
        s_q[w][n] = qw;
        s_T[w][n] = __dp4a(qw, 0x01010101u, 14u);
    }
    __syncwarp();

    // ---- Each thread: one output-quad (weights in regs) x 8 rows ----
    int g  = t >> 3;                             // row offset within group of 4
    int oq = t & 7;                              // which output float4
    float4 bias = s_bias[oq];
    float4* op = out + (size_t)tileRow * 8;

    if (!hz) {
        uint4 w0 = s_wp[oq * 4 + 0];
        uint4 w1 = s_wp[oq * 4 + 1];
        uint4 w2 = s_wp[oq * 4 + 2];
        uint4 w3 = s_wp[oq * 4 + 3];
        #pragma unroll 2
        for (int j = 0; j < 8; j++) {
            int r = 4 * j + g;
            uint4 q = ((const uint4*)s_q[w])[r];
            uint4 T = ((const uint4*)s_T[w])[r];
            float4 ov;
            ov.x = fmaf((float)quad_fast(q, T, w0), scale, bias.x);
            ov.y = fmaf((float)quad_fast(q, T, w1), scale, bias.y);
            ov.z = fmaf((float)quad_fast(q, T, w2), scale, bias.z);
            ov.w = fmaf((float)quad_fast(q, T, w3), scale, bias.w);
            if (tileRow + r < rows) op[(size_t)r * 8 + oq] = ov;
        }
    } else {
        #pragma unroll 2
        for (int j = 0; j < 8; j++) {
            int r = 4 * j + g;
            uint4 q = ((const uint4*)s_q[w])[r];
            float4 ov;
            ov.x = fmaf((float)quad_safe(q, s_wp[oq*4+0], s_wm[oq*4+0]), scale, bias.x);
            ov.y = fmaf((float)quad_safe(q, s_wp[oq*4+1], s_wm[oq*4+1]), scale, bias.y);
            ov.z = fmaf((float)quad_safe(q, s_wp[oq*4+2], s_wm[oq*4+2]), scale, bias.z);
            ov.w = fmaf((float)quad_safe(q, s_wp[oq*4+3], s_wm[oq*4+3]), scale, bias.w);
            if (tileRow + r < rows) op[(size_t)r * 8 + oq] = ov;
        }
    }
}

extern "C" void kernel_launch(void* const* d_in, const int* in_sizes, int n_in,
                              void* d_out, int out_size) {
    const float* Input  = (const float*)d_in[0];
    const float* weight = (const float*)d_in[1];
    const float* InMin  = (const float*)d_in[2];
    const float* InMax  = (const float*)d_in[3];
    float* out = (float*)d_out;

    int rows = in_sizes[0] / IN_DIM;

    quant_prep_kernel<<<1, 32>>>(weight, InMin, InMax);

    int blocks = (rows + TPB - 1) / TPB;
    quant_main_kernel<<<blocks, TPB>>>((const float4*)Input, (float4*)out, rows);
}

// round 7
// speedup vs baseline: 1.2399x; 1.2399x over previous
#include <cuda_runtime.h>
#include <cstdint>

#define IN_DIM   16
#define OUT_DIM  32
#define TPB      256
#define WARPS    8
#define RPB      256            // rows per block-tile
#define C15      286331154u     // ceil(2^32/15) (safe-path rounding)

__global__ void __launch_bounds__(TPB)
quant_fused_kernel(const float4* __restrict__ in, float4* __restrict__ out,
                   const float* __restrict__ weight,
                   const float* __restrict__ pInMin,
                   const float* __restrict__ pInMax,
                   int rows, int numTiles) {
    // 16B-aligned tiles first; explicit align so uint4 loads are legal.
    __shared__ __align__(16) uint32_t s_q[WARPS][128];  // 32 rows x 4 packed q chunks
    __shared__ __align__(16) uint32_t s_K[WARPS][128];  // 32 rows x 4 K-words (966-69b)<<16
    __shared__ uint4    s_wp[OUT_DIM];
    __shared__ uint4    s_wm[OUT_DIM];
    __shared__ float4   s_bias[OUT_DIM / 4];
    __shared__ int      s_A[WARPS][32];    // per-row A = sum_c floor(T_c/15)
    __shared__ int      s_hz;

    const int tid = threadIdx.x;
    const int w = tid >> 5, t = tid & 31;

    const float InMin = *pInMin, InMax = *pInMax;
    const float scale = InMax - InMin;
    const float qa = 15.0f / scale;
    const float qb = -InMin * 15.0f / scale;

    // ---- fused prep (warp 0): pack sign masks, bias, zero-flag ----
    if (tid < 32) {
        int o = tid;
        int anyz = 0, ssum = 0;
        uint32_t wp[4], wm[4];
        #pragma unroll
        for (int c = 0; c < 4; c++) {
            uint32_t p = 0, m = 0;
            #pragma unroll
            for (int j = 0; j < 4; j++) {
                float wv = weight[o * IN_DIM + c * 4 + j];
                int s = (wv > 0.0f) ? 1 : ((wv < 0.0f) ? -1 : 0);
                ssum += s;
                anyz |= (s == 0);
                if (s > 0) p |= 1u << (8 * j);
                if (s < 0) m |= 1u << (8 * j);
            }
            wp[c] = p; wm[c] = m;
        }
        s_wp[o] = make_uint4(wp[0], wp[1], wp[2], wp[3]);
        s_wm[o] = make_uint4(wm[0], wm[1], wm[2], wm[3]);
        ((float*)s_bias)[o] = InMin * (float)ssum;
        unsigned zb = __ballot_sync(0xffffffffu, anyz);
        if (o == 0) s_hz = (zb != 0u) ? 1 : 0;
    }
    __syncthreads();

    const int hz = s_hz;
    const int g  = t >> 3;          // row offset within group-of-4
    const int oq = t & 7;           // output float4 owned by this thread
    const float4 bias = s_bias[oq];

    // weights for this thread's 4 outputs, held in registers
    const uint4 w0 = s_wp[oq * 4 + 0];
    const uint4 w1 = s_wp[oq * 4 + 1];
    const uint4 w2 = s_wp[oq * 4 + 2];
    const uint4 w3 = s_wp[oq * 4 + 3];

    // ---- persistent tile loop ----
    for (int tile = blockIdx.x; tile < numTiles; tile += gridDim.x) {
        int tileRow = tile * RPB + w * 32;

        // prologue: coalesced load, quantize, build K words + A, stage
        const float4* ip = in + (size_t)tileRow * 4;
        #pragma unroll
        for (int i = 0; i < 4; i++) {
            int n = i * 32 + t;                    // = rlocal*4 + chunk
            float4 x = make_float4(0.f, 0.f, 0.f, 0.f);
            if (tileRow + (n >> 2) < rows) x = ip[n];
            int e0 = __float2int_rn(fmaf(x.x, qa, qb));
            int e1 = __float2int_rn(fmaf(x.y, qa, qb));
            int e2 = __float2int_rn(fmaf(x.z, qa, qb));
            int e3 = __float2int_rn(fmaf(x.w, qa, qb));
            uint32_t qw = __byte_perm(__byte_perm(e0, e1, 0x0040),
                                      __byte_perm(e2, e3, 0x0040), 0x5410);
            s_q[w][n] = qw;
            unsigned T = __dp4a(qw, 0x01010101u, 14u);   // S_c + 14, <= 74
            unsigned a = (69u * T) >> 10;                // floor(T/15), exact to 81
            unsigned b = T - 15u * a;                    // [0,14]
            s_K[w][n] = (966u - 69u * b) << 16;          // 966 = 69*14
            // A = sum of a over the 4 chunks of this row (lanes 4k..4k+3)
            int av = (int)a;
            av += __shfl_xor_sync(0xffffffffu, av, 1);
            av += __shfl_xor_sync(0xffffffffu, av, 2);
            if ((t & 3) == 0) s_A[w][i * 8 + (t >> 2)] = av;
        }
        __syncwarp();

        float4* op = out + (size_t)tileRow * 8;

        if (!hz) {
            #pragma unroll 2
            for (int j = 0; j < 8; j++) {
                int r = 4 * j + g;
                uint4 q = ((const uint4*)s_q[w])[r];
                uint4 K = ((const uint4*)s_K[w])[r];
                int   A = s_A[w][r];
                float4 ov;
                float* ovp = (float*)&ov;
                const uint4 ws[4] = {w0, w1, w2, w3};
                #pragma unroll
                for (int oi = 0; oi < 4; oi++) {
                    uint4 wv = ws[oi];
                    // per chunk: v = (yP+7)*0x450045 + K; lo lane->floor(x/15)<<10,
                    // hi lane->floor((x+14-b)/15)<<26; fields accumulate carry-free.
                    unsigned acc;
                    acc  = (__dp4a(q.x, wv.x, 7u) * 0x00450045u + K.x) & 0x1C001C00u;
                    acc += (__dp4a(q.y, wv.y, 7u) * 0x00450045u + K.y) & 0x1C001C00u;
                    acc += (__dp4a(q.z, wv.z, 7u) * 0x00450045u + K.z) & 0x1C001C00u;
                    acc += (__dp4a(q.w, wv.w, 7u) * 0x00450045u + K.w) & 0x1C001C00u;
                    int tot = (int)((acc >> 10) & 63u) + (int)(acc >> 26) - A;
                    ovp[oi] = fmaf((float)tot, scale, ((const float*)&bias)[oi]);
                }
                if (tileRow + r < rows) op[(size_t)r * 8 + oq] = ov;
            }
        } else {
            // safe path (some sign(w)==0): proven umulhi formulation
            #pragma unroll 2
            for (int j = 0; j < 8; j++) {
                int r = 4 * j + g;
                uint4 q = ((const uint4*)s_q[w])[r];
                float4 ov;
                float* ovp = (float*)&ov;
                #pragma unroll
                for (int oi = 0; oi < 4; oi++) {
                    uint4 wp = s_wp[oq * 4 + oi];
                    uint4 wm = s_wm[oq * 4 + oi];
                    unsigned rp0 = __dp4a(q.x, wp.x, 7u), rm0 = __dp4a(q.x, wm.x, 7u);
                    unsigned rp1 = __dp4a(q.y, wp.y, 7u), rm1 = __dp4a(q.y, wm.y, 7u);
                    unsigned rp2 = __dp4a(q.z, wp.z, 7u), rm2 = __dp4a(q.z, wm.z, 7u);
                    unsigned rp3 = __dp4a(q.w, wp.w, 7u), rm3 = __dp4a(q.w, wm.w, 7u);
                    int acc = (int)__umulhi(rp0, C15) - (int)__umulhi(rm0, C15)
                            + (int)__umulhi(rp1, C15) - (int)__umulhi(rm1, C15)
                            + (int)__umulhi(rp2, C15) - (int)__umulhi(rm2, C15)
                            + (int)__umulhi(rp3, C15) - (int)__umulhi(rm3, C15);
                    ovp[oi] = fmaf((float)acc, scale, ((const float*)&bias)[oi]);
                }
                if (tileRow + r < rows) op[(size_t)r * 8 + oq] = ov;
            }
        }
        __syncwarp();   // protect s_q/s_K/s_A before next tile's prologue
    }
}

extern "C" void kernel_launch(void* const* d_in, const int* in_sizes, int n_in,
                              void* d_out, int out_size) {
    const float* Input  = (const float*)d_in[0];
    const float* weight = (const float*)d_in[1];
    const float* InMin  = (const float*)d_in[2];
    const float* InMax  = (const float*)d_in[3];
    float* out = (float*)d_out;

    int rows = in_sizes[0] / IN_DIM;
    int numTiles = (rows + RPB - 1) / RPB;

    int blocks = 148 * 4;                 // persistent: 4 blocks/SM x 148 SMs
    if (blocks > numTiles) blocks = numTiles;

    quant_fused_kernel<<<blocks, TPB>>>((const float4*)Input, (float4*)out,
                                        weight, InMin, InMax, rows, numTiles);
}

// round 8
// speedup vs baseline: 1.4431x; 1.1639x over previous
#include <cuda_runtime.h>
#include <cstdint>

#define IN_DIM   16
#define OUT_DIM  32
#define TPB      256
#define WARPS    8
#define RPB      256            // rows per block-tile
#define C15      286331154u     // ceil(2^32/15) (safe-path rounding)

__global__ void __launch_bounds__(TPB, 4)
quant_fused_kernel(const float4* __restrict__ in, float4* __restrict__ out,
                   const float* __restrict__ weight,
                   const float* __restrict__ pInMin,
                   const float* __restrict__ pInMax,
                   int rows, int numTiles) {
    __shared__ __align__(16) uint32_t s_q[WARPS][128];  // 32 rows x 4 packed q chunks
    __shared__ __align__(16) uint32_t s_K[WARPS][128];  // 32 rows x 4 K-words (966-69b)<<16
    __shared__ uint32_t s_ab[WARPS][32];   // per-row: 4 bytes a_c (floor(T_c/15))
    __shared__ uint4    s_wp[OUT_DIM];
    __shared__ uint4    s_wm[OUT_DIM];
    __shared__ float4   s_bias[OUT_DIM / 4];
    __shared__ int      s_hz;

    const int tid = threadIdx.x;
    const int w = tid >> 5, t = tid & 31;

    const float InMin = *pInMin, InMax = *pInMax;
    const float scale = InMax - InMin;
    const float qa = 15.0f / scale;
    const float qb = -InMin * 15.0f / scale;

    // ---- fused prep (warp 0): pack sign masks, bias, zero-flag ----
    if (tid < 32) {
        int o = tid;
        int anyz = 0, ssum = 0;
        uint32_t wp[4], wm[4];
        #pragma unroll
        for (int c = 0; c < 4; c++) {
            uint32_t p = 0, m = 0;
            #pragma unroll
            for (int j = 0; j < 4; j++) {
                float wv = weight[o * IN_DIM + c * 4 + j];
                int s = (wv > 0.0f) ? 1 : ((wv < 0.0f) ? -1 : 0);
                ssum += s;
                anyz |= (s == 0);
                if (s > 0) p |= 1u << (8 * j);
                if (s < 0) m |= 1u << (8 * j);
            }
            wp[c] = p; wm[c] = m;
        }
        s_wp[o] = make_uint4(wp[0], wp[1], wp[2], wp[3]);
        s_wm[o] = make_uint4(wm[0], wm[1], wm[2], wm[3]);
        ((float*)s_bias)[o] = InMin * (float)ssum;
        unsigned zb = __ballot_sync(0xffffffffu, anyz);
        if (o == 0) s_hz = (zb != 0u) ? 1 : 0;
    }
    __syncthreads();

    const int g  = t >> 3;          // row offset within group-of-4
    const int oq = t & 7;           // output float4 owned by this thread
    const float4 bias = s_bias[oq];

    const uint4 w0 = s_wp[oq * 4 + 0];
    const uint4 w1 = s_wp[oq * 4 + 1];
    const uint4 w2 = s_wp[oq * 4 + 2];
    const uint4 w3 = s_wp[oq * 4 + 3];

    if (!s_hz) {
        // ================= HOT PATH (no zero-sign weights) =================
        for (int tile = blockIdx.x; tile < numTiles; tile += gridDim.x) {
            int tileRow = tile * RPB + w * 32;

            const float4* ip = in + (size_t)tileRow * 4;
            #pragma unroll
            for (int i = 0; i < 4; i++) {
                int n = i * 32 + t;                    // = rlocal*4 + chunk
                float4 x = make_float4(0.f, 0.f, 0.f, 0.f);
                if (tileRow + (n >> 2) < rows) x = ip[n];
                int e0 = __float2int_rn(fmaf(x.x, qa, qb));
                int e1 = __float2int_rn(fmaf(x.y, qa, qb));
                int e2 = __float2int_rn(fmaf(x.z, qa, qb));
                int e3 = __float2int_rn(fmaf(x.w, qa, qb));
                uint32_t qw = __byte_perm(__byte_perm(e0, e1, 0x0040),
                                          __byte_perm(e2, e3, 0x0040), 0x5410);
                s_q[w][n] = qw;
                unsigned T = __dp4a(qw, 0x01010101u, 14u);   // S_c + 14, <= 74
                unsigned a = (69u * T) >> 10;                // floor(T/15)
                unsigned b = T - 15u * a;                    // [0,14]
                s_K[w][n] = (966u - 69u * b) << 16;          // 966 = 69*14
                ((uint8_t*)s_ab[w])[n] = (uint8_t)a;         // byte per chunk
            }
            __syncwarp();

            float4* op = out + (size_t)tileRow * 8;
            #pragma unroll 2
            for (int j = 0; j < 8; j++) {
                int r = 4 * j + g;
                uint4 q = ((const uint4*)s_q[w])[r];
                uint4 K = ((const uint4*)s_K[w])[r];
                int   A = __dp4a(s_ab[w][r], 0x01010101u, 0u);
                float4 ov;
                // per chunk: v = (yP+7)*0x450045 + K; lo lane->floor(x/15)<<10,
                // hi lane->floor((x+14-b)/15)<<26; fields accumulate carry-free.
                unsigned acc;
                acc  = (__dp4a(q.x, w0.x, 7u) * 0x00450045u + K.x) & 0x1C001C00u;
                acc += (__dp4a(q.y, w0.y, 7u) * 0x00450045u + K.y) & 0x1C001C00u;
                acc += (__dp4a(q.z, w0.z, 7u) * 0x00450045u + K.z) & 0x1C001C00u;
                acc += (__dp4a(q.w, w0.w, 7u) * 0x00450045u + K.w) & 0x1C001C00u;
                ov.x = fmaf((float)((int)((acc >> 10) & 63u) + (int)(acc >> 26) - A), scale, bias.x);
                acc  = (__dp4a(q.x, w1.x, 7u) * 0x00450045u + K.x) & 0x1C001C00u;
                acc += (__dp4a(q.y, w1.y, 7u) * 0x00450045u + K.y) & 0x1C001C00u;
                acc += (__dp4a(q.z, w1.z, 7u) * 0x00450045u + K.z) & 0x1C001C00u;
                acc += (__dp4a(q.w, w1.w, 7u) * 0x00450045u + K.w) & 0x1C001C00u;
                ov.y = fmaf((float)((int)((acc >> 10) & 63u) + (int)(acc >> 26) - A), scale, bias.y);
                acc  = (__dp4a(q.x, w2.x, 7u) * 0x00450045u + K.x) & 0x1C001C00u;
                acc += (__dp4a(q.y, w2.y, 7u) * 0x00450045u + K.y) & 0x1C001C00u;
                acc += (__dp4a(q.z, w2.z, 7u) * 0x00450045u + K.z) & 0x1C001C00u;
                acc += (__dp4a(q.w, w2.w, 7u) * 0x00450045u + K.w) & 0x1C001C00u;
                ov.z = fmaf((float)((int)((acc >> 10) & 63u) + (int)(acc >> 26) - A), scale, bias.z);
                acc  = (__dp4a(q.x, w3.x, 7u) * 0x00450045u + K.x) & 0x1C001C00u;
                acc += (__dp4a(q.y, w3.y, 7u) * 0x00450045u + K.y) & 0x1C001C00u;
                acc += (__dp4a(q.z, w3.z, 7u) * 0x00450045u + K.z) & 0x1C001C00u;
                acc += (__dp4a(q.w, w3.w, 7u) * 0x00450045u + K.w) & 0x1C001C00u;
                ov.w = fmaf((float)((int)((acc >> 10) & 63u) + (int)(acc >> 26) - A), scale, bias.w);
                if (tileRow + r < rows) op[(size_t)r * 8 + oq] = ov;
            }
            __syncwarp();
        }
    } else {
        // ================= SAFE PATH (some sign(w)==0) =================
        for (int tile = blockIdx.x; tile < numTiles; tile += gridDim.x) {
            int tileRow = tile * RPB + w * 32;

            const float4* ip = in + (size_t)tileRow * 4;
            #pragma unroll
            for (int i = 0; i < 4; i++) {
                int n = i * 32 + t;
                float4 x = make_float4(0.f, 0.f, 0.f, 0.f);
                if (tileRow + (n >> 2) < rows) x = ip[n];
                int e0 = __float2int_rn(fmaf(x.x, qa, qb));
                int e1 = __float2int_rn(fmaf(x.y, qa, qb));
                int e2 = __float2int_rn(fmaf(x.z, qa, qb));
                int e3 = __float2int_rn(fmaf(x.w, qa, qb));
                s_q[w][n] = __byte_perm(__byte_perm(e0, e1, 0x0040),
                                        __byte_perm(e2, e3, 0x0040), 0x5410);
            }
            __syncwarp();

            float4* op = out + (size_t)tileRow * 8;
            #pragma unroll 2
            for (int j = 0; j < 8; j++) {
                int r = 4 * j + g;
                uint4 q = ((const uint4*)s_q[w])[r];
                float4 ov;
                float* ovp = (float*)&ov;
                #pragma unroll
                for (int oi = 0; oi < 4; oi++) {
                    uint4 wp = s_wp[oq * 4 + oi];
                    uint4 wm = s_wm[oq * 4 + oi];
                    unsigned rp0 = __dp4a(q.x, wp.x, 7u), rm0 = __dp4a(q.x, wm.x, 7u);
                    unsigned rp1 = __dp4a(q.y, wp.y, 7u), rm1 = __dp4a(q.y, wm.y, 7u);
                    unsigned rp2 = __dp4a(q.z, wp.z, 7u), rm2 = __dp4a(q.z, wm.z, 7u);
                    unsigned rp3 = __dp4a(q.w, wp.w, 7u), rm3 = __dp4a(q.w, wm.w, 7u);
                    int acc = (int)__umulhi(rp0, C15) - (int)__umulhi(rm0, C15)
                            + (int)__umulhi(rp1, C15) - (int)__umulhi(rm1, C15)
                            + (int)__umulhi(rp2, C15) - (int)__umulhi(rm2, C15)
                            + (int)__umulhi(rp3, C15) - (int)__umulhi(rm3, C15);
                    ovp[oi] = fmaf((float)acc, scale, ((const float*)&bias)[oi]);
                }
                if (tileRow + r < rows) op[(size_t)r * 8 + oq] = ov;
            }
            __syncwarp();
        }
    }
}

extern "C" void kernel_launch(void* const* d_in, const int* in_sizes, int n_in,
                              void* d_out, int out_size) {
    const float* Input  = (const float*)d_in[0];
    const float* weight = (const float*)d_in[1];
    const float* InMin  = (const float*)d_in[2];
    const float* InMax  = (const float*)d_in[3];
    float* out = (float*)d_out;

    int rows = in_sizes[0] / IN_DIM;
    int numTiles = (rows + RPB - 1) / RPB;

    int blocks = 148 * 4;                 // one resident wave at 4 CTAs/SM
    if (blocks > numTiles) blocks = numTiles;

    quant_fused_kernel<<<blocks, TPB>>>((const float4*)Input, (float4*)out,
                                        weight, InMin, InMax, rows, numTiles);
}